// round 1
// baseline (speedup 1.0000x reference)
#include <cuda_runtime.h>
#include <math.h>

#define DHID 1536
#define SEQ  896
#define BAT  4
#define NMAX 5313

#define BM 64
#define BN 64
#define BK 16

// LayerNorm scratch: [BAT, SEQ, DHID] fp32 (22 MB, static device array per rules)
__device__ float g_xn[(size_t)BAT * SEQ * DHID];

__device__ __forceinline__ float softplus_f(float z) {
    // matches log1p(exp(z)) with large-z passthrough; error negligible at z>20
    if (z > 20.0f) return z;
    return log1pf(__expf(z));
}

// One block per (batch,row). 256 threads.
__global__ void __launch_bounds__(256) ln_kernel(
    const float* __restrict__ x, const int* __restrict__ head_idx,
    const float* __restrict__ g0, const float* __restrict__ be0,
    const float* __restrict__ g1, const float* __restrict__ be1,
    const float* __restrict__ g2, const float* __restrict__ be2)
{
    int row = blockIdx.x;          // 0 .. BAT*SEQ-1
    int b   = row / SEQ;
    int head = head_idx[b];
    if (head >= 3) return;         // ZeroHead: xn unused

    const float* gamma = (head == 0) ? g0 : (head == 1) ? g1 : g2;
    const float* beta  = (head == 0) ? be0 : (head == 1) ? be1 : be2;

    const float4* xr = (const float4*)(x + (size_t)row * DHID);
    float4* xo = (float4*)(g_xn + (size_t)row * DHID);
    const float4* gv = (const float4*)gamma;
    const float4* bv = (const float4*)beta;

    int tid = threadIdx.x;
    float s = 0.f, ss = 0.f;
    for (int i = tid; i < DHID / 4; i += blockDim.x) {
        float4 t = xr[i];
        s  += t.x + t.y + t.z + t.w;
        ss += t.x * t.x + t.y * t.y + t.z * t.z + t.w * t.w;
    }
    // block reduction
    __shared__ float red[64];
    #pragma unroll
    for (int o = 16; o > 0; o >>= 1) {
        s  += __shfl_down_sync(0xffffffffu, s,  o);
        ss += __shfl_down_sync(0xffffffffu, ss, o);
    }
    int wid = tid >> 5, lid = tid & 31;
    if (lid == 0) { red[wid] = s; red[32 + wid] = ss; }
    __syncthreads();
    __shared__ float mu_sh, rstd_sh;
    if (tid == 0) {
        float S1 = 0.f, S2 = 0.f;
        #pragma unroll
        for (int i = 0; i < 8; i++) { S1 += red[i]; S2 += red[32 + i]; }
        float mu  = S1 / (float)DHID;
        float var = S2 / (float)DHID - mu * mu;   // biased var, torch-style
        mu_sh   = mu;
        rstd_sh = rsqrtf(var + 1e-5f);
    }
    __syncthreads();
    float mu = mu_sh, rstd = rstd_sh;
    for (int i = tid; i < DHID / 4; i += blockDim.x) {
        float4 t = xr[i];
        float4 g = gv[i];
        float4 be = bv[i];
        float4 o;
        o.x = (t.x - mu) * rstd * g.x + be.x;
        o.y = (t.y - mu) * rstd * g.y + be.y;
        o.z = (t.z - mu) * rstd * g.z + be.z;
        o.w = (t.w - mu) * rstd * g.w + be.w;
        xo[i] = o;
    }
}

// Tiled fp32 GEMM + bias + softplus + zero-pad.
// grid: (ceil(NMAX/BN)=84, SEQ/BM=14, BAT=4), 256 threads, 4x4 per thread.
__global__ void __launch_bounds__(256) head_gemm_kernel(
    const int* __restrict__ head_idx,
    const float* __restrict__ W0, const float* __restrict__ bb0,
    const float* __restrict__ W1, const float* __restrict__ bb1,
    const float* __restrict__ W2, const float* __restrict__ bb2,
    float* __restrict__ out)
{
    int bz   = blockIdx.z;
    int row0 = blockIdx.y * BM;
    int col0 = blockIdx.x * BN;

    int head = head_idx[bz];
    int n; const float* W; const float* bias;
    if (head == 0)      { n = 5313; W = W0; bias = bb0; }
    else if (head == 1) { n = 1643; W = W1; bias = bb1; }
    else if (head == 2) { n = 128;  W = W2; bias = bb2; }
    else                { n = 0;    W = nullptr; bias = nullptr; }

    int tid = threadIdx.x;
    float* outb = out + (size_t)bz * SEQ * NMAX;

    if (col0 >= n) {
        // pure padding (or ZeroHead) tile: fill zeros, clipped to NMAX
        for (int i = tid; i < BM * BN; i += 256) {
            int r = i / BN;
            int c = col0 + (i % BN);
            if (c < NMAX) outb[(size_t)(row0 + r) * NMAX + c] = 0.0f;
        }
        return;
    }

    __shared__ float As[BK][BM + 4];   // stride 68 floats: 16B-aligned rows, low-conflict
    __shared__ float Bs[BK][BN + 4];

    const float* xb = g_xn + ((size_t)bz * SEQ + row0) * DHID;

    int lr  = tid >> 2;          // 0..63 : tile row (A) / tile col (B=W row)
    int lk4 = (tid & 3) * 4;     // 0,4,8,12 : k sub-offset (float4)

    int ty = tid >> 4;           // 0..15 : output row group
    int tx = tid & 15;           // 0..15 : output col group

    float acc[4][4];
    #pragma unroll
    for (int i = 0; i < 4; i++)
        #pragma unroll
        for (int j = 0; j < 4; j++) acc[i][j] = 0.0f;

    bool wvalid = (col0 + lr) < n;
    const float* wrow = wvalid ? (W + (size_t)(col0 + lr) * DHID) : nullptr;
    const float* arow = xb + (size_t)lr * DHID;

    for (int k0 = 0; k0 < DHID; k0 += BK) {
        float4 av = *(const float4*)(arow + k0 + lk4);
        float4 bvv = make_float4(0.f, 0.f, 0.f, 0.f);
        if (wvalid) bvv = *(const float4*)(wrow + k0 + lk4);

        __syncthreads();
        As[lk4 + 0][lr] = av.x;
        As[lk4 + 1][lr] = av.y;
        As[lk4 + 2][lr] = av.z;
        As[lk4 + 3][lr] = av.w;
        Bs[lk4 + 0][lr] = bvv.x;
        Bs[lk4 + 1][lr] = bvv.y;
        Bs[lk4 + 2][lr] = bvv.z;
        Bs[lk4 + 3][lr] = bvv.w;
        __syncthreads();

        #pragma unroll
        for (int kk = 0; kk < BK; kk++) {
            float4 a = *(const float4*)&As[kk][ty * 4];
            float4 bq = *(const float4*)&Bs[kk][tx * 4];
            float ar[4] = {a.x, a.y, a.z, a.w};
            float br[4] = {bq.x, bq.y, bq.z, bq.w};
            #pragma unroll
            for (int i = 0; i < 4; i++)
                #pragma unroll
                for (int j = 0; j < 4; j++)
                    acc[i][j] = fmaf(ar[i], br[j], acc[i][j]);
        }
    }

    // epilogue: bias + softplus inside [0,n), zero in [n,NMAX)
    float biasr[4];
    #pragma unroll
    for (int j = 0; j < 4; j++) {
        int c = col0 + tx * 4 + j;
        biasr[j] = (c < n) ? bias[c] : 0.0f;
    }
    #pragma unroll
    for (int i = 0; i < 4; i++) {
        int r = row0 + ty * 4 + i;
        float* orow = outb + (size_t)r * NMAX;
        #pragma unroll
        for (int j = 0; j < 4; j++) {
            int c = col0 + tx * 4 + j;
            if (c < n) {
                orow[c] = softplus_f(acc[i][j] + biasr[j]);
            } else if (c < NMAX) {
                orow[c] = 0.0f;
            }
        }
    }
}

extern "C" void kernel_launch(void* const* d_in, const int* in_sizes, int n_in,
                              void* d_out, int out_size) {
    const float* x        = (const float*)d_in[0];
    const int*   head_idx = (const int*)d_in[1];
    const float* g0 = (const float*)d_in[2];
    const float* be0 = (const float*)d_in[3];
    const float* W0 = (const float*)d_in[4];
    const float* bb0 = (const float*)d_in[5];
    const float* g1 = (const float*)d_in[6];
    const float* be1 = (const float*)d_in[7];
    const float* W1 = (const float*)d_in[8];
    const float* bb1 = (const float*)d_in[9];
    const float* g2 = (const float*)d_in[10];
    const float* be2 = (const float*)d_in[11];
    const float* W2 = (const float*)d_in[12];
    const float* bb2 = (const float*)d_in[13];
    float* out = (float*)d_out;

    ln_kernel<<<BAT * SEQ, 256>>>(x, head_idx, g0, be0, g1, be1, g2, be2);

    dim3 grid((NMAX + BN - 1) / BN, SEQ / BM, BAT);
    head_gemm_kernel<<<grid, 256>>>(head_idx, W0, bb0, W1, bb1, W2, bb2, out);
}

// round 5
// speedup vs baseline: 1.9594x; 1.9594x over previous
#include <cuda_runtime.h>
#include <cuda_bf16.h>
#include <math.h>
#include <stdint.h>

#define DHID 1536
#define SEQ  896
#define BAT  4
#define NMAX 5313
#define N0 5313
#define N1 1643
#define N2 128
#define WROWS (N0 + N1 + N2)

#define BM 128
#define BN 128
#define BK 32
#define NC (DHID / BK)        // 48

// ---------------- static device scratch ----------------
__device__ __align__(16) __nv_bfloat16 g_ahi[(size_t)BAT * SEQ * DHID];
__device__ __align__(16) __nv_bfloat16 g_alo[(size_t)BAT * SEQ * DHID];
__device__ __align__(16) __nv_bfloat16 g_whi[(size_t)WROWS * DHID];
__device__ __align__(16) __nv_bfloat16 g_wlo[(size_t)WROWS * DHID];

// ---------------- helpers ----------------
__device__ __forceinline__ uint32_t smem_u32(const void* p) {
    uint32_t a;
    asm("{ .reg .u64 t; cvta.to.shared.u64 t, %1; cvt.u32.u64 %0, t; }" : "=r"(a) : "l"(p));
    return a;
}
#define CP_ASYNC16(dst, src) \
    asm volatile("cp.async.cg.shared.global [%0], [%1], 16;" :: "r"(dst), "l"(src))
#define CP_COMMIT()  asm volatile("cp.async.commit_group;" ::: "memory")
#define CP_WAIT1()   asm volatile("cp.async.wait_group 1;" ::: "memory")

#define LDM_X4(r0,r1,r2,r3,addr) \
    asm volatile("ldmatrix.sync.aligned.m8n8.x4.shared.b16 {%0,%1,%2,%3}, [%4];" \
        : "=r"(r0),"=r"(r1),"=r"(r2),"=r"(r3) : "r"(addr))

#define MMA_BF16(d, a, b0v, b1v) \
    asm volatile("mma.sync.aligned.m16n8k16.row.col.f32.bf16.bf16.f32 " \
        "{%0,%1,%2,%3}, {%4,%5,%6,%7}, {%8,%9}, {%0,%1,%2,%3};" \
        : "+f"((d)[0]), "+f"((d)[1]), "+f"((d)[2]), "+f"((d)[3]) \
        : "r"((a)[0]), "r"((a)[1]), "r"((a)[2]), "r"((a)[3]), "r"(b0v), "r"(b1v))

__device__ __forceinline__ float softplus_f(float z) {
    if (z > 20.0f) return z;
    return log1pf(__expf(z));
}
__device__ __forceinline__ void split_bf16(float v, __nv_bfloat16& hi, __nv_bfloat16& lo) {
    hi = __float2bfloat16(v);
    lo = __float2bfloat16(v - __bfloat162float(hi));
}

// ---------------- prep: LN->split + W->split (only needed heads) ----------------
__global__ void __launch_bounds__(256) prep_kernel(
    const float* __restrict__ x, const int* __restrict__ head_idx,
    const float* __restrict__ g0, const float* __restrict__ be0, const float* __restrict__ W0,
    const float* __restrict__ g1, const float* __restrict__ be1, const float* __restrict__ W1,
    const float* __restrict__ g2, const float* __restrict__ be2, const float* __restrict__ W2)
{
    int blk = blockIdx.x;
    int tid = threadIdx.x;

    if (blk < BAT * SEQ) {                     // ---- LayerNorm + split ----
        int row = blk;
        int b = row / SEQ;
        int head = head_idx[b];
        if (head >= 3) return;
        const float* gamma = (head == 0) ? g0 : (head == 1) ? g1 : g2;
        const float* beta  = (head == 0) ? be0 : (head == 1) ? be1 : be2;

        const float4* xr = (const float4*)(x + (size_t)row * DHID);
        float s = 0.f, ss = 0.f;
        for (int i = tid; i < DHID / 4; i += 256) {
            float4 t = xr[i];
            s  += t.x + t.y + t.z + t.w;
            ss += t.x * t.x + t.y * t.y + t.z * t.z + t.w * t.w;
        }
        __shared__ float red[64];
        #pragma unroll
        for (int o = 16; o > 0; o >>= 1) {
            s  += __shfl_down_sync(0xffffffffu, s,  o);
            ss += __shfl_down_sync(0xffffffffu, ss, o);
        }
        int wid = tid >> 5, lid = tid & 31;
        if (lid == 0) { red[wid] = s; red[32 + wid] = ss; }
        __syncthreads();
        __shared__ float mu_sh, rstd_sh;
        if (tid == 0) {
            float S1 = 0.f, S2 = 0.f;
            #pragma unroll
            for (int i = 0; i < 8; i++) { S1 += red[i]; S2 += red[32 + i]; }
            float mu = S1 / (float)DHID;
            float var = S2 / (float)DHID - mu * mu;
            mu_sh = mu; rstd_sh = rsqrtf(var + 1e-5f);
        }
        __syncthreads();
        float mu = mu_sh, rstd = rstd_sh;
        const float4* gv = (const float4*)gamma;
        const float4* bv = (const float4*)beta;
        uint2* rhi = (uint2*)(g_ahi + (size_t)row * DHID);
        uint2* rlo = (uint2*)(g_alo + (size_t)row * DHID);
        for (int i = tid; i < DHID / 4; i += 256) {
            float4 t = xr[i], g = gv[i], be = bv[i];
            float o[4] = {(t.x - mu) * rstd * g.x + be.x, (t.y - mu) * rstd * g.y + be.y,
                          (t.z - mu) * rstd * g.z + be.z, (t.w - mu) * rstd * g.w + be.w};
            __align__(8) __nv_bfloat16 hi[4], lo[4];
            #pragma unroll
            for (int k = 0; k < 4; k++) split_bf16(o[k], hi[k], lo[k]);
            rhi[i] = *(uint2*)hi;
            rlo[i] = *(uint2*)lo;
        }
    } else {                                   // ---- W split (needed heads only) ----
        int mask = (1 << head_idx[0]) | (1 << head_idx[1]) |
                   (1 << head_idx[2]) | (1 << head_idx[3]);
        size_t wb = blk - BAT * SEQ;
        size_t base = wb * 2048 + (size_t)tid * 8;
        const size_t B0 = (size_t)N0 * DHID, B1 = B0 + (size_t)N1 * DHID;
        const float* src;
        int h;
        if (base < B0)      { src = W0 + base;        h = 0; }
        else if (base < B1) { src = W1 + (base - B0); h = 1; }
        else                { src = W2 + (base - B1); h = 2; }
        if (!(mask & (1 << h))) return;
        float4 v0 = ((const float4*)src)[0];
        float4 v1 = ((const float4*)src)[1];
        float vv[8] = {v0.x, v0.y, v0.z, v0.w, v1.x, v1.y, v1.z, v1.w};
        __align__(16) __nv_bfloat16 hi[8], lo[8];
        #pragma unroll
        for (int k = 0; k < 8; k++) split_bf16(vv[k], hi[k], lo[k]);
        *(uint4*)(g_whi + base) = *(uint4*)hi;
        *(uint4*)(g_wlo + base) = *(uint4*)lo;
    }
}

// ---------------- HMMA GEMM ----------------
// smem: per stage: A_hi[128][40] A_lo B_hi B_lo bf16 (80B rows)
#define ROWB   80
#define MATB   (128 * ROWB)          // 10240
#define STGB   (4 * MATB)            // 40960
#define A_HI(s) ((s) * STGB)
#define A_LO(s) ((s) * STGB + MATB)
#define B_HI(s) ((s) * STGB + 2 * MATB)
#define B_LO(s) ((s) * STGB + 3 * MATB)
#define SMEM_TOTAL (2 * STGB)

__global__ void __launch_bounds__(256, 1) head_gemm_mma(
    const int* __restrict__ head_idx,
    const float* __restrict__ b0p, const float* __restrict__ b1p, const float* __restrict__ b2p,
    float* __restrict__ out)
{
    extern __shared__ char smem[];
    int tid = threadIdx.x;
    int bz = blockIdx.z;
    int row0 = blockIdx.y * BM;
    int col0 = blockIdx.x * BN;

    int head = head_idx[bz];
    int n; const __nv_bfloat16 *whi, *wlo; const float* bias;
    if (head == 0)      { n = N0; whi = g_whi; wlo = g_wlo; bias = b0p; }
    else if (head == 1) { n = N1; whi = g_whi + (size_t)N0 * DHID; wlo = g_wlo + (size_t)N0 * DHID; bias = b1p; }
    else if (head == 2) { n = N2; whi = g_whi + (size_t)(N0 + N1) * DHID; wlo = g_wlo + (size_t)(N0 + N1) * DHID; bias = b2p; }
    else                { n = 0; whi = nullptr; wlo = nullptr; bias = nullptr; }

    float* outb = out + (size_t)bz * SEQ * NMAX;

    if (col0 >= n) {            // padding / ZeroHead tile: zero-fill (scalar, NMAX odd)
        for (int i = tid; i < BM * BN; i += 256) {
            int r = i >> 7;                     // /BN
            int c = col0 + (i & 127);
            if (c < NMAX) outb[(size_t)(row0 + r) * NMAX + c] = 0.0f;
        }
        return;
    }

    uint32_t sb = smem_u32(smem);
    int wid = tid >> 5, lid = tid & 31;
    int wm = wid >> 2;          // 0..1  (64 rows each)
    int wn = wid & 3;           // 0..3  (32 cols each)

    const __nv_bfloat16* ahi = g_ahi + ((size_t)bz * SEQ + row0) * DHID;
    const __nv_bfloat16* alo = g_alo + ((size_t)bz * SEQ + row0) * DHID;

    auto load_chunk = [&](int c, int s) {
        int k0 = c * BK;
        #pragma unroll
        for (int t = 0; t < 2; t++) {
            int u = tid + t * 256;         // 0..511
            int row = u >> 2, seg = u & 3;
            uint32_t dof = row * ROWB + seg * 16;
            const char* sa1 = (const char*)(ahi + (size_t)row * DHID + k0) + seg * 16;
            const char* sa2 = (const char*)(alo + (size_t)row * DHID + k0) + seg * 16;
            CP_ASYNC16(sb + A_HI(s) + dof, sa1);
            CP_ASYNC16(sb + A_LO(s) + dof, sa2);
            int gr = col0 + row;
            uint32_t d1 = sb + B_HI(s) + dof;
            uint32_t d2 = sb + B_LO(s) + dof;
            if (gr < n) {
                const char* s1 = (const char*)(whi + (size_t)gr * DHID + k0) + seg * 16;
                const char* s2 = (const char*)(wlo + (size_t)gr * DHID + k0) + seg * 16;
                CP_ASYNC16(d1, s1);
                CP_ASYNC16(d2, s2);
            } else {
                asm volatile("st.shared.v4.b32 [%0], {%1,%1,%1,%1};" :: "r"(d1), "r"(0u) : "memory");
                asm volatile("st.shared.v4.b32 [%0], {%1,%1,%1,%1};" :: "r"(d2), "r"(0u) : "memory");
            }
        }
    };

    float acc[4][4][4];
    #pragma unroll
    for (int i = 0; i < 4; i++)
        #pragma unroll
        for (int j = 0; j < 4; j++)
            #pragma unroll
            for (int k = 0; k < 4; k++) acc[i][j][k] = 0.f;

    load_chunk(0, 0); CP_COMMIT();
    load_chunk(1, 1); CP_COMMIT();

    // ldmatrix lane addressing (constant across chunks)
    uint32_t aRow = (uint32_t)(wm * 64 + (lid & 15)) * ROWB + (uint32_t)(lid >> 4) * 16;
    int q = lid >> 3;
    uint32_t bRowBase = (uint32_t)(wn * 32 + ((q >> 1) << 3) + (lid & 7)) * ROWB + (uint32_t)(q & 1) * 16;

    for (int c = 0; c < NC; c++) {
        int s = c & 1;
        CP_WAIT1();
        __syncthreads();

        #pragma unroll
        for (int kk = 0; kk < 2; kk++) {
            uint32_t kb = kk * 32;
            uint32_t ah[4][4], al[4][4], bh[2][4], bl[2][4];
            #pragma unroll
            for (int mi = 0; mi < 4; mi++) {
                uint32_t ra = sb + A_HI(s) + aRow + (uint32_t)(mi * 16) * ROWB + kb;
                LDM_X4(ah[mi][0], ah[mi][1], ah[mi][2], ah[mi][3], ra);
                LDM_X4(al[mi][0], al[mi][1], al[mi][2], al[mi][3], ra + MATB);
            }
            #pragma unroll
            for (int g = 0; g < 2; g++) {
                uint32_t rb = sb + B_HI(s) + bRowBase + (uint32_t)(g * 16) * ROWB + kb;
                LDM_X4(bh[g][0], bh[g][1], bh[g][2], bh[g][3], rb);
                LDM_X4(bl[g][0], bl[g][1], bl[g][2], bl[g][3], rb + MATB);
            }
            #pragma unroll
            for (int mi = 0; mi < 4; mi++)
                #pragma unroll
                for (int g = 0; g < 2; g++)
                    #pragma unroll
                    for (int h = 0; h < 2; h++) {
                        int ni = g * 2 + h;
                        MMA_BF16(acc[mi][ni], ah[mi], bh[g][2 * h], bh[g][2 * h + 1]);
                        MMA_BF16(acc[mi][ni], ah[mi], bl[g][2 * h], bl[g][2 * h + 1]);
                        MMA_BF16(acc[mi][ni], al[mi], bh[g][2 * h], bh[g][2 * h + 1]);
                    }
        }

        __syncthreads();
        if (c + 2 < NC) load_chunk(c + 2, s);
        CP_COMMIT();
    }

    // ---- epilogue: bias + softplus + zero-pad (scalar stores; NMAX odd) ----
    #pragma unroll
    for (int mi = 0; mi < 4; mi++) {
        int r = row0 + wm * 64 + mi * 16 + (lid >> 2);
        float* o0 = outb + (size_t)r * NMAX;
        float* o1 = o0 + 8 * NMAX;
        #pragma unroll
        for (int ni = 0; ni < 4; ni++) {
            int cc = col0 + wn * 32 + ni * 8 + (lid & 3) * 2;
            float* a = acc[mi][ni];
            #pragma unroll
            for (int j = 0; j < 2; j++) {
                int c = cc + j;
                if (c < n) {
                    float bv = bias[c];
                    o0[c] = softplus_f(a[0 + j] + bv);
                    o1[c] = softplus_f(a[2 + j] + bv);
                } else if (c < NMAX) {
                    o0[c] = 0.f;
                    o1[c] = 0.f;
                }
            }
        }
    }
}

// ---------------- launch ----------------
extern "C" void kernel_launch(void* const* d_in, const int* in_sizes, int n_in,
                              void* d_out, int out_size) {
    const float* x        = (const float*)d_in[0];
    const int*   head_idx = (const int*)d_in[1];
    const float* g0 = (const float*)d_in[2];
    const float* be0 = (const float*)d_in[3];
    const float* W0 = (const float*)d_in[4];
    const float* bb0 = (const float*)d_in[5];
    const float* g1 = (const float*)d_in[6];
    const float* be1 = (const float*)d_in[7];
    const float* W1 = (const float*)d_in[8];
    const float* bb1 = (const float*)d_in[9];
    const float* g2 = (const float*)d_in[10];
    const float* be2 = (const float*)d_in[11];
    const float* W2 = (const float*)d_in[12];
    const float* bb2 = (const float*)d_in[13];
    float* out = (float*)d_out;

    int wblocks = (int)(((size_t)WROWS * DHID) / 2048);   // 5313
    prep_kernel<<<BAT * SEQ + wblocks, 256>>>(x, head_idx,
                                              g0, be0, W0, g1, be1, W1, g2, be2, W2);

    cudaFuncSetAttribute(head_gemm_mma, cudaFuncAttributeMaxDynamicSharedMemorySize, SMEM_TOTAL);
    dim3 grid((NMAX + BN - 1) / BN, SEQ / BM, BAT);   // 42 x 7 x 4
    head_gemm_mma<<<grid, 256, SMEM_TOTAL>>>(head_idx, bb0, bb1, bb2, out);
}

// round 6
// speedup vs baseline: 2.2859x; 1.1666x over previous
#include <cuda_runtime.h>
#include <cuda_bf16.h>
#include <math.h>
#include <stdint.h>

#define DHID 1536
#define SEQ  896
#define BAT  4
#define NMAX 5313
#define N0 5313
#define N1 1643
#define N2 128
#define WROWS (N0 + N1 + N2)

#define BM 128
#define BN 128
#define BK 32
#define NC (DHID / BK)        // 48

// ---------------- static device scratch ----------------
__device__ __align__(16) __nv_bfloat16 g_ahi[(size_t)BAT * SEQ * DHID];
__device__ __align__(16) __nv_bfloat16 g_alo[(size_t)BAT * SEQ * DHID];
__device__ __align__(16) __nv_bfloat16 g_whi[(size_t)WROWS * DHID];
__device__ __align__(16) __nv_bfloat16 g_wlo[(size_t)WROWS * DHID];

// ---------------- helpers ----------------
__device__ __forceinline__ uint32_t smem_u32(const void* p) {
    uint32_t a;
    asm("{ .reg .u64 t; cvta.to.shared.u64 t, %1; cvt.u32.u64 %0, t; }" : "=r"(a) : "l"(p));
    return a;
}
#define CP_ASYNC16(dst, src) \
    asm volatile("cp.async.cg.shared.global [%0], [%1], 16;" :: "r"(dst), "l"(src))
#define CP_COMMIT()  asm volatile("cp.async.commit_group;" ::: "memory")
#define CP_WAIT1()   asm volatile("cp.async.wait_group 1;" ::: "memory")

#define LDM_X4(r0,r1,r2,r3,addr) \
    asm volatile("ldmatrix.sync.aligned.m8n8.x4.shared.b16 {%0,%1,%2,%3}, [%4];" \
        : "=r"(r0),"=r"(r1),"=r"(r2),"=r"(r3) : "r"(addr))

#define MMA_BF16(d, a0,a1,a2,a3, b0v, b1v) \
    asm volatile("mma.sync.aligned.m16n8k16.row.col.f32.bf16.bf16.f32 " \
        "{%0,%1,%2,%3}, {%4,%5,%6,%7}, {%8,%9}, {%0,%1,%2,%3};" \
        : "+f"((d)[0]), "+f"((d)[1]), "+f"((d)[2]), "+f"((d)[3]) \
        : "r"(a0), "r"(a1), "r"(a2), "r"(a3), "r"(b0v), "r"(b1v))

__device__ __forceinline__ float softplus_f(float z) {
    if (z > 20.0f) return z;
    return log1pf(__expf(z));
}
__device__ __forceinline__ void split_bf16(float v, __nv_bfloat16& hi, __nv_bfloat16& lo) {
    hi = __float2bfloat16(v);
    lo = __float2bfloat16(v - __bfloat162float(hi));
}

// ---------------- prep: LN->split + W->split (only needed heads) ----------------
__global__ void __launch_bounds__(256) prep_kernel(
    const float* __restrict__ x, const int* __restrict__ head_idx,
    const float* __restrict__ g0, const float* __restrict__ be0, const float* __restrict__ W0,
    const float* __restrict__ g1, const float* __restrict__ be1, const float* __restrict__ W1,
    const float* __restrict__ g2, const float* __restrict__ be2, const float* __restrict__ W2)
{
    int blk = blockIdx.x;
    int tid = threadIdx.x;

    if (blk < BAT * SEQ) {                     // ---- LayerNorm + split ----
        int row = blk;
        int b = row / SEQ;
        int head = head_idx[b];
        if (head >= 3) return;
        const float* gamma = (head == 0) ? g0 : (head == 1) ? g1 : g2;
        const float* beta  = (head == 0) ? be0 : (head == 1) ? be1 : be2;

        const float4* xr = (const float4*)(x + (size_t)row * DHID);
        float s = 0.f, ss = 0.f;
        for (int i = tid; i < DHID / 4; i += 256) {
            float4 t = xr[i];
            s  += t.x + t.y + t.z + t.w;
            ss += t.x * t.x + t.y * t.y + t.z * t.z + t.w * t.w;
        }
        __shared__ float red[64];
        #pragma unroll
        for (int o = 16; o > 0; o >>= 1) {
            s  += __shfl_down_sync(0xffffffffu, s,  o);
            ss += __shfl_down_sync(0xffffffffu, ss, o);
        }
        int wid = tid >> 5, lid = tid & 31;
        if (lid == 0) { red[wid] = s; red[32 + wid] = ss; }
        __syncthreads();
        __shared__ float mu_sh, rstd_sh;
        if (tid == 0) {
            float S1 = 0.f, S2 = 0.f;
            #pragma unroll
            for (int i = 0; i < 8; i++) { S1 += red[i]; S2 += red[32 + i]; }
            float mu = S1 / (float)DHID;
            float var = S2 / (float)DHID - mu * mu;
            mu_sh = mu; rstd_sh = rsqrtf(var + 1e-5f);
        }
        __syncthreads();
        float mu = mu_sh, rstd = rstd_sh;
        const float4* gv = (const float4*)gamma;
        const float4* bv = (const float4*)beta;
        uint2* rhi = (uint2*)(g_ahi + (size_t)row * DHID);
        uint2* rlo = (uint2*)(g_alo + (size_t)row * DHID);
        for (int i = tid; i < DHID / 4; i += 256) {
            float4 t = xr[i], g = gv[i], be = bv[i];
            float o[4] = {(t.x - mu) * rstd * g.x + be.x, (t.y - mu) * rstd * g.y + be.y,
                          (t.z - mu) * rstd * g.z + be.z, (t.w - mu) * rstd * g.w + be.w};
            __align__(8) __nv_bfloat16 hi[4], lo[4];
            #pragma unroll
            for (int k = 0; k < 4; k++) split_bf16(o[k], hi[k], lo[k]);
            rhi[i] = *(uint2*)hi;
            rlo[i] = *(uint2*)lo;
        }
    } else {                                   // ---- W split (needed heads only) ----
        int mask = (1 << head_idx[0]) | (1 << head_idx[1]) |
                   (1 << head_idx[2]) | (1 << head_idx[3]);
        size_t wb = blk - BAT * SEQ;
        size_t base = wb * 2048 + (size_t)tid * 8;
        const size_t B0 = (size_t)N0 * DHID, B1 = B0 + (size_t)N1 * DHID;
        const float* src;
        int h;
        if (base < B0)      { src = W0 + base;        h = 0; }
        else if (base < B1) { src = W1 + (base - B0); h = 1; }
        else                { src = W2 + (base - B1); h = 2; }
        if (!(mask & (1 << h))) return;
        float4 v0 = ((const float4*)src)[0];
        float4 v1 = ((const float4*)src)[1];
        float vv[8] = {v0.x, v0.y, v0.z, v0.w, v1.x, v1.y, v1.z, v1.w};
        __align__(16) __nv_bfloat16 hi[8], lo[8];
        #pragma unroll
        for (int k = 0; k < 8; k++) split_bf16(vv[k], hi[k], lo[k]);
        *(uint4*)(g_whi + base) = *(uint4*)hi;
        *(uint4*)(g_wlo + base) = *(uint4*)lo;
    }
}

// ---------------- HMMA GEMM ----------------
// smem per stage: A_hi[128][40] A_lo B_hi B_lo bf16 (80B rows)
#define ROWB   80
#define MATB   (128 * ROWB)          // 10240
#define STGB   (4 * MATB)            // 40960
#define A_HI(s) ((s) * STGB)
#define A_LO(s) ((s) * STGB + MATB)
#define B_HI(s) ((s) * STGB + 2 * MATB)
#define B_LO(s) ((s) * STGB + 3 * MATB)
#define SMEM_TOTAL (2 * STGB)

__global__ void __launch_bounds__(256, 2) head_gemm_mma(
    const int* __restrict__ head_idx,
    const float* __restrict__ b0p, const float* __restrict__ b1p, const float* __restrict__ b2p,
    float* __restrict__ out)
{
    extern __shared__ char smem[];
    int tid = threadIdx.x;
    int bz = blockIdx.z;
    int row0 = blockIdx.y * BM;
    int col0 = blockIdx.x * BN;

    int head = head_idx[bz];
    int n; const __nv_bfloat16 *whi, *wlo; const float* bias;
    if (head == 0)      { n = N0; whi = g_whi; wlo = g_wlo; bias = b0p; }
    else if (head == 1) { n = N1; whi = g_whi + (size_t)N0 * DHID; wlo = g_wlo + (size_t)N0 * DHID; bias = b1p; }
    else if (head == 2) { n = N2; whi = g_whi + (size_t)(N0 + N1) * DHID; wlo = g_wlo + (size_t)(N0 + N1) * DHID; bias = b2p; }
    else                { n = 0; whi = nullptr; wlo = nullptr; bias = nullptr; }

    float* outb = out + (size_t)bz * SEQ * NMAX;

    if (col0 >= n) {            // padding / ZeroHead tile: zero-fill (scalar, NMAX odd)
        for (int i = tid; i < BM * BN; i += 256) {
            int r = i >> 7;
            int c = col0 + (i & 127);
            if (c < NMAX) outb[(size_t)(row0 + r) * NMAX + c] = 0.0f;
        }
        return;
    }

    uint32_t sb = smem_u32(smem);
    int wid = tid >> 5, lid = tid & 31;
    int wm = wid >> 2;          // 0..1  (64 rows each)
    int wn = wid & 3;           // 0..3  (32 cols each)

    const __nv_bfloat16* ahi = g_ahi + ((size_t)bz * SEQ + row0) * DHID;
    const __nv_bfloat16* alo = g_alo + ((size_t)bz * SEQ + row0) * DHID;

    auto load_chunk = [&](int c, int s) {
        int k0 = c * BK;
        #pragma unroll
        for (int t = 0; t < 2; t++) {
            int u = tid + t * 256;         // 0..511
            int row = u >> 2, seg = u & 3;
            uint32_t dof = row * ROWB + seg * 16;
            const char* sa1 = (const char*)(ahi + (size_t)row * DHID + k0) + seg * 16;
            const char* sa2 = (const char*)(alo + (size_t)row * DHID + k0) + seg * 16;
            CP_ASYNC16(sb + A_HI(s) + dof, sa1);
            CP_ASYNC16(sb + A_LO(s) + dof, sa2);
            int gr = col0 + row;
            uint32_t d1 = sb + B_HI(s) + dof;
            uint32_t d2 = sb + B_LO(s) + dof;
            if (gr < n) {
                const char* s1 = (const char*)(whi + (size_t)gr * DHID + k0) + seg * 16;
                const char* s2 = (const char*)(wlo + (size_t)gr * DHID + k0) + seg * 16;
                CP_ASYNC16(d1, s1);
                CP_ASYNC16(d2, s2);
            } else {
                asm volatile("st.shared.v4.b32 [%0], {%1,%1,%1,%1};" :: "r"(d1), "r"(0u) : "memory");
                asm volatile("st.shared.v4.b32 [%0], {%1,%1,%1,%1};" :: "r"(d2), "r"(0u) : "memory");
            }
        }
    };

    float acc[4][4][4];
    #pragma unroll
    for (int i = 0; i < 4; i++)
        #pragma unroll
        for (int j = 0; j < 4; j++)
            #pragma unroll
            for (int k = 0; k < 4; k++) acc[i][j][k] = 0.f;

    load_chunk(0, 0); CP_COMMIT();
    load_chunk(1, 1); CP_COMMIT();

    // ldmatrix lane addressing (constant across chunks)
    uint32_t aRow = (uint32_t)(wm * 64 + (lid & 15)) * ROWB + (uint32_t)(lid >> 4) * 16;
    int q = lid >> 3;
    uint32_t bRowBase = (uint32_t)(wn * 32 + ((q >> 1) << 3) + (lid & 7)) * ROWB + (uint32_t)(q & 1) * 16;

    for (int c = 0; c < NC; c++) {
        int s = c & 1;
        CP_WAIT1();
        __syncthreads();

        #pragma unroll
        for (int kk = 0; kk < 2; kk++) {
            uint32_t kb = kk * 32;
            // B fragments for this k-step: 16 regs live
            uint32_t bh[2][4], bl[2][4];
            #pragma unroll
            for (int g = 0; g < 2; g++) {
                uint32_t rb = sb + B_HI(s) + bRowBase + (uint32_t)(g * 16) * ROWB + kb;
                LDM_X4(bh[g][0], bh[g][1], bh[g][2], bh[g][3], rb);
                LDM_X4(bl[g][0], bl[g][1], bl[g][2], bl[g][3], rb + MATB);
            }
            // A fragments just-in-time per mi: 8 regs live
            #pragma unroll
            for (int mi = 0; mi < 4; mi++) {
                uint32_t ra = sb + A_HI(s) + aRow + (uint32_t)(mi * 16) * ROWB + kb;
                uint32_t ah0, ah1, ah2, ah3, al0, al1, al2, al3;
                LDM_X4(ah0, ah1, ah2, ah3, ra);
                LDM_X4(al0, al1, al2, al3, ra + MATB);
                #pragma unroll
                for (int g = 0; g < 2; g++)
                    #pragma unroll
                    for (int h = 0; h < 2; h++) {
                        int ni = g * 2 + h;
                        MMA_BF16(acc[mi][ni], ah0, ah1, ah2, ah3, bh[g][2 * h], bh[g][2 * h + 1]);
                        MMA_BF16(acc[mi][ni], ah0, ah1, ah2, ah3, bl[g][2 * h], bl[g][2 * h + 1]);
                        MMA_BF16(acc[mi][ni], al0, al1, al2, al3, bh[g][2 * h], bh[g][2 * h + 1]);
                    }
            }
        }

        __syncthreads();
        if (c + 2 < NC) load_chunk(c + 2, s);
        CP_COMMIT();
    }

    // ---- epilogue: bias + softplus + zero-pad (scalar stores; NMAX odd) ----
    #pragma unroll
    for (int mi = 0; mi < 4; mi++) {
        int r = row0 + wm * 64 + mi * 16 + (lid >> 2);
        float* o0 = outb + (size_t)r * NMAX;
        float* o1 = o0 + 8 * NMAX;
        #pragma unroll
        for (int ni = 0; ni < 4; ni++) {
            int cc = col0 + wn * 32 + ni * 8 + (lid & 3) * 2;
            float* a = acc[mi][ni];
            #pragma unroll
            for (int j = 0; j < 2; j++) {
                int c = cc + j;
                if (c < n) {
                    float bv = bias[c];
                    o0[c] = softplus_f(a[0 + j] + bv);
                    o1[c] = softplus_f(a[2 + j] + bv);
                } else if (c < NMAX) {
                    o0[c] = 0.f;
                    o1[c] = 0.f;
                }
            }
        }
    }
}

// ---------------- launch ----------------
extern "C" void kernel_launch(void* const* d_in, const int* in_sizes, int n_in,
                              void* d_out, int out_size) {
    const float* x        = (const float*)d_in[0];
    const int*   head_idx = (const int*)d_in[1];
    const float* g0 = (const float*)d_in[2];
    const float* be0 = (const float*)d_in[3];
    const float* W0 = (const float*)d_in[4];
    const float* bb0 = (const float*)d_in[5];
    const float* g1 = (const float*)d_in[6];
    const float* be1 = (const float*)d_in[7];
    const float* W1 = (const float*)d_in[8];
    const float* bb1 = (const float*)d_in[9];
    const float* g2 = (const float*)d_in[10];
    const float* be2 = (const float*)d_in[11];
    const float* W2 = (const float*)d_in[12];
    const float* bb2 = (const float*)d_in[13];
    float* out = (float*)d_out;

    int wblocks = (int)(((size_t)WROWS * DHID) / 2048);   // 5313
    prep_kernel<<<BAT * SEQ + wblocks, 256>>>(x, head_idx,
                                              g0, be0, W0, g1, be1, W1, g2, be2, W2);

    cudaFuncSetAttribute(head_gemm_mma, cudaFuncAttributeMaxDynamicSharedMemorySize, SMEM_TOTAL);
    dim3 grid((NMAX + BN - 1) / BN, SEQ / BM, BAT);   // 42 x 7 x 4
    head_gemm_mma<<<grid, 256, SMEM_TOTAL>>>(head_idx, bb0, bb1, bb2, out);
}